// round 9
// baseline (speedup 1.0000x reference)
#include <cuda_runtime.h>
#include <math.h>

// Problem constants
#define BSZ   2
#define CC    256
#define NN    4096          // H*W
#define HEADS 8
#define HD    32
#define BA    8             // BSZ*AREA
#define NA    1024          // NN/AREA
#define MLPD  307

#define QKV_BSTRIDE (768*NN)
#define C_BSTRIDE   (CC*NN)

// ---------------- scratch ----------------------------------------------------
__device__ float g_qkv[BSZ * 768 * NN];
__device__ float g_pe [BSZ * CC  * NN];
__device__ float g_att[BSZ * CC  * NN];
__device__ float g_x1 [BSZ * CC  * NN];
__device__ float g_m  [BSZ * MLPD* NN];

// ---------------- f32x2 helpers ----------------------------------------------
__device__ __forceinline__ void ffma2(unsigned long long &d, unsigned long long a,
                                      unsigned long long b, unsigned long long c) {
    asm("fma.rn.f32x2 %0, %1, %2, %3;" : "=l"(d) : "l"(a), "l"(b), "l"(c));
}
__device__ __forceinline__ unsigned long long pk2(float lo, float hi) {
    unsigned long long u;
    asm("mov.b64 %0, {%1,%2};" : "=l"(u) : "f"(lo), "f"(hi));
    return u;
}
__device__ __forceinline__ float2 upk2(unsigned long long u) {
    float2 v;
    asm("mov.b64 {%0,%1}, %2;" : "=f"(v.x), "=f"(v.y) : "l"(u));
    return v;
}
__device__ __forceinline__ void fadd2(unsigned long long &d, unsigned long long a,
                                      unsigned long long b) {
    asm("add.rn.f32x2 %0, %1, %2;" : "=l"(d) : "l"(a), "l"(b));
}
__device__ __forceinline__ float ex2(float x) {
    float r;
    asm("ex2.approx.ftz.f32 %0, %1;" : "=f"(r) : "f"(x));
    return r;
}

// ---------------- conv1x1 GEMM: 128m x 128n tile, 8x8/thread, double-buffered -
// (identical to R5 — verified at ~250us aggregate)
__global__ __launch_bounds__(256)
void gemm_kernel(const float* __restrict__ A,
                 const float* __restrict__ Bm,
                 const float* __restrict__ B2,
                 const float* __restrict__ sc,
                 const float* __restrict__ bi,
                 const float* __restrict__ res,
                 float* __restrict__ Cout,
                 int M, int K,
                 long sB, long sC, long sR, int epi)
{
    __shared__ __align__(16) float As[2][16][128];
    __shared__ __align__(16) float Bs[2][16][128];

    const int b = blockIdx.z;
    const float* Bb  = Bm + (long)b * sB;
    const float* B2b = B2 ? (B2 + (long)b * sB) : nullptr;
    const float* Rb  = res ? (res + (long)b * sR) : nullptr;
    float* Cb = Cout + (long)b * sC;

    const int m0 = blockIdx.y * 128;
    const int n0 = blockIdx.x * 128;
    const int tid = threadIdx.x;
    const int tx = tid & 15, ty = tid >> 4;

    const int am = tid >> 1;
    const int ak = (tid & 1) * 8;
    const int bk = tid >> 4;
    const int bn = (tid & 15) * 8;

    const bool k_vec = ((K & 3) == 0);
    const int nkt = (K + 15) >> 4;

    unsigned long long acc[8][4] = {};
    float ar[8], br[8];

    #define LOAD_TILE(KT)                                                      \
    {                                                                          \
        const int k0 = (KT) * 16;                                              \
        const int gm = m0 + am;                                                \
        _Pragma("unroll") for (int i = 0; i < 8; i++) ar[i] = 0.f;             \
        if (gm < M) {                                                          \
            if (k_vec && (k0 + ak + 7 < K)) {                                  \
                const float4 a0 = *(const float4*)(A + (long)gm * K + k0 + ak);     \
                const float4 a1 = *(const float4*)(A + (long)gm * K + k0 + ak + 4); \
                ar[0]=a0.x; ar[1]=a0.y; ar[2]=a0.z; ar[3]=a0.w;                \
                ar[4]=a1.x; ar[5]=a1.y; ar[6]=a1.z; ar[7]=a1.w;                \
            } else {                                                           \
                _Pragma("unroll") for (int i = 0; i < 8; i++) {                \
                    const int gk = k0 + ak + i;                                \
                    if (gk < K) ar[i] = A[(long)gm * K + gk];                  \
                }                                                              \
            }                                                                  \
        }                                                                      \
        const int gk = k0 + bk;                                                \
        if (gk < K) {                                                          \
            const float* p = Bb + (long)gk * NN + n0 + bn;                     \
            const float4 v0 = *(const float4*)p;                               \
            const float4 v1 = *(const float4*)(p + 4);                         \
            br[0]=v0.x; br[1]=v0.y; br[2]=v0.z; br[3]=v0.w;                    \
            br[4]=v1.x; br[5]=v1.y; br[6]=v1.z; br[7]=v1.w;                    \
            if (B2b) {                                                         \
                const float* q = B2b + (long)gk * NN + n0 + bn;                \
                const float4 w0 = *(const float4*)q;                           \
                const float4 w1 = *(const float4*)(q + 4);                     \
                br[0]+=w0.x; br[1]+=w0.y; br[2]+=w0.z; br[3]+=w0.w;            \
                br[4]+=w1.x; br[5]+=w1.y; br[6]+=w1.z; br[7]+=w1.w;            \
            }                                                                  \
        } else {                                                               \
            _Pragma("unroll") for (int i = 0; i < 8; i++) br[i] = 0.f;         \
        }                                                                      \
    }

    #define STORE_TILE(BUF)                                                    \
    {                                                                          \
        _Pragma("unroll") for (int i = 0; i < 8; i++) As[BUF][ak + i][am] = ar[i]; \
        *(float4*)&Bs[BUF][bk][bn]     = make_float4(br[0], br[1], br[2], br[3]);  \
        *(float4*)&Bs[BUF][bk][bn + 4] = make_float4(br[4], br[5], br[6], br[7]);  \
    }

    LOAD_TILE(0)
    STORE_TILE(0)
    __syncthreads();

    for (int kt = 0; kt < nkt; kt++) {
        const int buf = kt & 1;
        const bool more = (kt + 1 < nkt);
        if (more) LOAD_TILE(kt + 1)

        #pragma unroll
        for (int kk = 0; kk < 16; kk++) {
            const float4 a0 = *(const float4*)&As[buf][kk][ty * 8];
            const float4 a1 = *(const float4*)&As[buf][kk][ty * 8 + 4];
            const ulonglong2 c0 = *(const ulonglong2*)&Bs[buf][kk][tx * 8];
            const ulonglong2 c1 = *(const ulonglong2*)&Bs[buf][kk][tx * 8 + 4];
            const unsigned long long bb0 = c0.x, bb1 = c0.y, bb2 = c1.x, bb3 = c1.y;
            const float av[8] = {a0.x,a0.y,a0.z,a0.w,a1.x,a1.y,a1.z,a1.w};
            #pragma unroll
            for (int i = 0; i < 8; i++) {
                const unsigned long long ap = pk2(av[i], av[i]);
                ffma2(acc[i][0], ap, bb0, acc[i][0]);
                ffma2(acc[i][1], ap, bb1, acc[i][1]);
                ffma2(acc[i][2], ap, bb2, acc[i][2]);
                ffma2(acc[i][3], ap, bb3, acc[i][3]);
            }
        }
        if (more) {
            STORE_TILE(buf ^ 1)
            __syncthreads();
        }
    }

    #pragma unroll
    for (int i = 0; i < 8; i++) {
        const int m = m0 + ty * 8 + i;
        if (m >= M) break;
        const float scl = sc[m], bia = bi[m];
        float o[8];
        #pragma unroll
        for (int t = 0; t < 4; t++) {
            const float2 v = upk2(acc[i][t]);
            o[2 * t] = v.x; o[2 * t + 1] = v.y;
        }
        #pragma unroll
        for (int t = 0; t < 8; t++) {
            float v = o[t] * scl + bia;
            if (epi == 1) v = v / (1.f + __expf(-v));
            o[t] = v;
        }
        const long base = (long)m * NN + n0 + tx * 8;
        if (Rb) {
            const float4 r0 = *(const float4*)(Rb + base);
            const float4 r1 = *(const float4*)(Rb + base + 4);
            o[0] += r0.x; o[1] += r0.y; o[2] += r0.z; o[3] += r0.w;
            o[4] += r1.x; o[5] += r1.y; o[6] += r1.z; o[7] += r1.w;
        }
        *(float4*)(Cb + base)     = make_float4(o[0], o[1], o[2], o[3]);
        *(float4*)(Cb + base + 4) = make_float4(o[4], o[5], o[6], o[7]);
    }
    #undef LOAD_TILE
    #undef STORE_TILE
}

// ---------------- depthwise 3x3 ----------------------------------------------
__global__ void dwconv_kernel(const float* __restrict__ w_pe,
                              const float* __restrict__ s,
                              const float* __restrict__ bi)
{
    const int bc = blockIdx.y;
    const int b = bc >> 8, c = bc & 255;
    const int hw = blockIdx.x * 256 + threadIdx.x;
    const int h = hw >> 6, w = hw & 63;
    const float* src = g_qkv + (long)b * QKV_BSTRIDE + (long)(512 + c) * NN;
    float acc = 0.f;
    #pragma unroll
    for (int kh = 0; kh < 3; kh++) {
        const int hh = h + kh - 1;
        if (hh < 0 || hh >= 64) continue;
        #pragma unroll
        for (int kw = 0; kw < 3; kw++) {
            const int ww = w + kw - 1;
            if (ww < 0 || ww >= 64) continue;
            acc += src[hh * 64 + ww] * w_pe[c * 9 + kh * 3 + kw];
        }
    }
    g_pe[(long)b * C_BSTRIDE + (long)c * NN + hw] = acc * s[c] + bi[c];
}

// ---- area attention: R5 inner loop, 128-thr CTAs x3/SM for occupancy --------
// Reshape mapping verified in R1 (rel_err 2.7e-8):
//   q/k: addr = (f>>21)*QKV_BSTRIDE + (f&(2^21-1)), f = ba*2^19 + cc*1024 + n'
//   v:   addr = (f>>20)*QKV_BSTRIDE + 512*NN + (f&(2^20-1))
// softmax without max-subtraction is fp32-exact for these magnitudes.
// scale*log2(e) folded into q; exp via ex2.approx (MUFU.EX2).
#define BK 128
#define KROW 36   // 144 B rows: 16B-aligned for LDS.128

__global__ __launch_bounds__(128, 3)
void attn_kernel()
{
    __shared__ __align__(16) float ks[BK][KROW];
    __shared__ __align__(16) float vs[BK][KROW];

    const int ba = blockIdx.y >> 3;
    const int h  = blockIdx.y & 7;
    const int q0 = blockIdx.x * 256;
    const int j  = threadIdx.x;          // 128 threads
    const int nq0 = q0 + j;
    const int nq1 = q0 + j + 128;

    // 1/sqrt(32) * log2(e)
    const float scale = 0.17677669529663687f * 1.4426950408889634f;

    const long qflat0 = (long)ba * 524288 + (long)(h * HD) * 1024;
    const long kflat0 = qflat0 + 256 * 1024;
    const long vflat0 = (long)ba * 262144 + (long)(h * HD) * 1024;

    unsigned long long qa[16], qb[16], oa[16], ob[16];
    #pragma unroll
    for (int d2 = 0; d2 < 16; d2++) {
        const long f0 = qflat0 + (long)(2 * d2) * 1024;
        const long f1 = f0 + 1024;
        const long g0 = f0 + nq0, g1 = f1 + nq0;
        const float a0 = g_qkv[(g0 >> 21) * QKV_BSTRIDE + (g0 & 2097151)] * scale;
        const float a1 = g_qkv[(g1 >> 21) * QKV_BSTRIDE + (g1 & 2097151)] * scale;
        qa[d2] = pk2(a0, a1);
        const long e0 = f0 + nq1, e1 = f1 + nq1;
        const float b0 = g_qkv[(e0 >> 21) * QKV_BSTRIDE + (e0 & 2097151)] * scale;
        const float b1 = g_qkv[(e1 >> 21) * QKV_BSTRIDE + (e1 & 2097151)] * scale;
        qb[d2] = pk2(b0, b1);
        oa[d2] = 0ull; ob[d2] = 0ull;
    }
    float lia = 0.f, lib = 0.f;

    for (int m0 = 0; m0 < NA; m0 += BK) {
        // k/v tile: 32 d x 128 m each; float4 over m, coalesced LDG
        #pragma unroll
        for (int r = 0; r < 8; r++) {
            const int idx = r * 128 + j;          // 0..1023
            const int d = idx >> 5, m4 = (idx & 31) * 4;
            const long fk = kflat0 + (long)d * 1024 + m0 + m4;
            const float4 kv = *(const float4*)&g_qkv[(fk >> 21) * QKV_BSTRIDE + (fk & 2097151)];
            ks[m4 + 0][d] = kv.x; ks[m4 + 1][d] = kv.y;
            ks[m4 + 2][d] = kv.z; ks[m4 + 3][d] = kv.w;
            const long fv = vflat0 + (long)d * 1024 + m0 + m4;
            const float4 vv = *(const float4*)&g_qkv[(fv >> 20) * QKV_BSTRIDE + 512 * NN + (fv & 1048575)];
            vs[m4 + 0][d] = vv.x; vs[m4 + 1][d] = vv.y;
            vs[m4 + 2][d] = vv.z; vs[m4 + 3][d] = vv.w;
        }
        __syncthreads();
        #pragma unroll 2
        for (int m = 0; m < BK; m++) {
            unsigned long long sa0 = 0ull, sa1 = 0ull, sb0 = 0ull, sb1 = 0ull;
            const ulonglong2* kr = (const ulonglong2*)&ks[m][0];
            #pragma unroll
            for (int t = 0; t < 8; t++) {
                const ulonglong2 kk2 = kr[t];
                ffma2(sa0, qa[2 * t],     kk2.x, sa0);
                ffma2(sa1, qa[2 * t + 1], kk2.y, sa1);
                ffma2(sb0, qb[2 * t],     kk2.x, sb0);
                ffma2(sb1, qb[2 * t + 1], kk2.y, sb1);
            }
            unsigned long long sa, sb;
            fadd2(sa, sa0, sa1);
            fadd2(sb, sb0, sb1);
            const float2 fa = upk2(sa), fb = upk2(sb);
            const float pa = ex2(fa.x + fa.y);
            const float pb = ex2(fb.x + fb.y);
            lia += pa; lib += pb;
            const unsigned long long pa2 = pk2(pa, pa);
            const unsigned long long pb2 = pk2(pb, pb);
            const ulonglong2* vr = (const ulonglong2*)&vs[m][0];
            #pragma unroll
            for (int t = 0; t < 8; t++) {
                const ulonglong2 vv = vr[t];
                ffma2(oa[2 * t],     pa2, vv.x, oa[2 * t]);
                ffma2(oa[2 * t + 1], pa2, vv.y, oa[2 * t + 1]);
                ffma2(ob[2 * t],     pb2, vv.x, ob[2 * t]);
                ffma2(ob[2 * t + 1], pb2, vv.y, ob[2 * t + 1]);
            }
        }
        __syncthreads();
    }

    const float inva = 1.f / lia, invb = 1.f / lib;
    #pragma unroll
    for (int d2 = 0; d2 < 16; d2++) {
        const float2 va = upk2(oa[d2]);
        const float2 vb = upk2(ob[d2]);
        const long f0 = vflat0 + (long)(2 * d2) * 1024;
        const long f1 = f0 + 1024;
        const long g0 = f0 + nq0, g1 = f1 + nq0;
        g_att[(g0 >> 20) * C_BSTRIDE + (g0 & 1048575)] = va.x * inva;
        g_att[(g1 >> 20) * C_BSTRIDE + (g1 & 1048575)] = va.y * inva;
        const long e0 = f0 + nq1, e1 = f1 + nq1;
        g_att[(e0 >> 20) * C_BSTRIDE + (e0 & 1048575)] = vb.x * invb;
        g_att[(e1 >> 20) * C_BSTRIDE + (e1 & 1048575)] = vb.y * invb;
    }
}

// ---------------- launch -------------------------------------------------------
extern "C" void kernel_launch(void* const* d_in, const int* in_sizes, int n_in,
                              void* d_out, int out_size)
{
    const float* x      = (const float*)d_in[0];
    const float* w_qk   = (const float*)d_in[1];
    const float* s_qk   = (const float*)d_in[2];
    const float* b_qk   = (const float*)d_in[3];
    const float* w_v    = (const float*)d_in[4];
    const float* s_v    = (const float*)d_in[5];
    const float* b_v    = (const float*)d_in[6];
    const float* w_pe   = (const float*)d_in[7];
    const float* s_pe   = (const float*)d_in[8];
    const float* b_pe   = (const float*)d_in[9];
    const float* w_proj = (const float*)d_in[10];
    const float* s_proj = (const float*)d_in[11];
    const float* b_proj = (const float*)d_in[12];
    const float* w_m1   = (const float*)d_in[13];
    const float* s_m1   = (const float*)d_in[14];
    const float* b_m1   = (const float*)d_in[15];
    const float* w_m2   = (const float*)d_in[16];
    const float* s_m2   = (const float*)d_in[17];
    const float* b_m2   = (const float*)d_in[18];
    float* out = (float*)d_out;

    float *qkv, *pe, *att, *x1, *mb;
    cudaGetSymbolAddress((void**)&qkv, g_qkv);
    cudaGetSymbolAddress((void**)&pe,  g_pe);
    cudaGetSymbolAddress((void**)&att, g_att);
    cudaGetSymbolAddress((void**)&x1,  g_x1);
    cudaGetSymbolAddress((void**)&mb,  g_m);

    // qk -> g_qkv channels [0,512)
    gemm_kernel<<<dim3(32, 4, BSZ), 256>>>(w_qk, x, nullptr, s_qk, b_qk, nullptr,
        qkv, 512, 256, (long)C_BSTRIDE, (long)QKV_BSTRIDE, 0, 0);
    // v -> g_qkv channels [512,768)
    gemm_kernel<<<dim3(32, 2, BSZ), 256>>>(w_v, x, nullptr, s_v, b_v, nullptr,
        qkv + 512 * NN, 256, 256, (long)C_BSTRIDE, (long)QKV_BSTRIDE, 0, 0);
    // pe = dwconv3x3(v)
    dwconv_kernel<<<dim3(16, BSZ * CC), 256>>>(w_pe, s_pe, b_pe);
    // area attention -> g_att : 256 blocks of 128 threads, 3 CTAs/SM
    attn_kernel<<<dim3(NA / 256, BA * HEADS), 128>>>();
    // x1 = x + conv1x1(att + pe, w_proj)
    gemm_kernel<<<dim3(32, 2, BSZ), 256>>>(w_proj, att, pe, s_proj, b_proj, x,
        x1, 256, 256, (long)C_BSTRIDE, (long)C_BSTRIDE, (long)C_BSTRIDE, 0);
    // m = silu(conv1x1(x1, w_m1))
    gemm_kernel<<<dim3(32, 3, BSZ), 256>>>(w_m1, x1, nullptr, s_m1, b_m1, nullptr,
        mb, MLPD, 256, (long)C_BSTRIDE, (long)MLPD * NN, 0, 1);
    // out = x1 + conv1x1(m, w_m2)
    gemm_kernel<<<dim3(32, 2, BSZ), 256>>>(w_m2, mb, nullptr, s_m2, b_m2, x1,
        out, 256, MLPD, (long)MLPD * NN, (long)C_BSTRIDE, (long)C_BSTRIDE, 0);
}

// round 10
// speedup vs baseline: 1.7119x; 1.7119x over previous
#include <cuda_runtime.h>
#include <cuda_fp16.h>
#include <math.h>

// Problem constants
#define BSZ   2
#define CC    256
#define NN    4096          // H*W
#define HEADS 8
#define HD    32
#define BA    8             // BSZ*AREA
#define NA    1024          // NN/AREA
#define MLPD  307

#define QKV_BSTRIDE (768*NN)
#define C_BSTRIDE   (CC*NN)

// ---------------- scratch ----------------------------------------------------
__device__ float g_qkv[BSZ * 768 * NN];
__device__ float g_pe [BSZ * CC  * NN];
__device__ float g_att[BSZ * CC  * NN];
__device__ float g_x1 [BSZ * CC  * NN];
__device__ float g_m  [BSZ * MLPD* NN];

// ---------------- f32x2 / misc helpers ---------------------------------------
__device__ __forceinline__ void ffma2(unsigned long long &d, unsigned long long a,
                                      unsigned long long b, unsigned long long c) {
    asm("fma.rn.f32x2 %0, %1, %2, %3;" : "=l"(d) : "l"(a), "l"(b), "l"(c));
}
__device__ __forceinline__ unsigned long long pk2(float lo, float hi) {
    unsigned long long u;
    asm("mov.b64 %0, {%1,%2};" : "=l"(u) : "f"(lo), "f"(hi));
    return u;
}
__device__ __forceinline__ float2 upk2(unsigned long long u) {
    float2 v;
    asm("mov.b64 {%0,%1}, %2;" : "=f"(v.x), "=f"(v.y) : "l"(u));
    return v;
}
__device__ __forceinline__ void fadd2(unsigned long long &d, unsigned long long a,
                                      unsigned long long b) {
    asm("add.rn.f32x2 %0, %1, %2;" : "=l"(d) : "l"(a), "l"(b));
}
__device__ __forceinline__ float ex2(float x) {
    float r;
    asm("ex2.approx.ftz.f32 %0, %1;" : "=f"(r) : "f"(x));
    return r;
}
__device__ __forceinline__ unsigned smem_u32(const void* p) {
    return (unsigned)__cvta_generic_to_shared(p);
}
__device__ __forceinline__ void ldsm4(unsigned* r, unsigned addr) {
    asm volatile("ldmatrix.sync.aligned.m8n8.x4.shared.b16 {%0,%1,%2,%3}, [%4];"
        : "=r"(r[0]), "=r"(r[1]), "=r"(r[2]), "=r"(r[3]) : "r"(addr));
}
__device__ __forceinline__ void ldsm4t(unsigned* r, unsigned addr) {
    asm volatile("ldmatrix.sync.aligned.m8n8.x4.trans.shared.b16 {%0,%1,%2,%3}, [%4];"
        : "=r"(r[0]), "=r"(r[1]), "=r"(r[2]), "=r"(r[3]) : "r"(addr));
}
__device__ __forceinline__ void mma16816(float* c, const unsigned* a,
                                         unsigned b0, unsigned b1) {
    asm volatile("mma.sync.aligned.m16n8k16.row.col.f32.f16.f16.f32 "
        "{%0,%1,%2,%3},{%4,%5,%6,%7},{%8,%9},{%0,%1,%2,%3};"
        : "+f"(c[0]), "+f"(c[1]), "+f"(c[2]), "+f"(c[3])
        : "r"(a[0]), "r"(a[1]), "r"(a[2]), "r"(a[3]), "r"(b0), "r"(b1));
}

// ---- conv1x1 GEMM via HMMA (fp16 in, fp32 acc): 64m x 128n, 8 warps ---------
// C[b][m][n] = epi((sum_k A[m][k]*(Bm[b][k][n](+B2))) * sc[m] + bi[m]) (+ res)
#define BKK 32
#define AP  (BKK + 8)      // As row pitch (halves)
#define BP  (128 + 8)      // Bs row pitch (halves)

__global__ __launch_bounds__(256)
void gemm_kernel(const float* __restrict__ A,
                 const float* __restrict__ Bm,
                 const float* __restrict__ B2,
                 const float* __restrict__ sc,
                 const float* __restrict__ bi,
                 const float* __restrict__ res,
                 float* __restrict__ Cout,
                 int M, int K,
                 long sB, long sC, long sR, int epi)
{
    __shared__ __align__(16) __half As[2][64][AP];
    __shared__ __align__(16) __half Bs[2][BKK][BP];

    const int b = blockIdx.z;
    const float* Bb  = Bm + (long)b * sB;
    const float* B2b = B2 ? (B2 + (long)b * sB) : nullptr;
    const float* Rb  = res ? (res + (long)b * sR) : nullptr;
    float* Cb = Cout + (long)b * sC;

    const int m0 = blockIdx.y * 64;
    const int n0 = blockIdx.x * 128;
    const int tid  = threadIdx.x;
    const int lane = tid & 31;
    const int wid  = tid >> 5;
    const int wm = (wid >> 2) * 32;       // 0 / 32
    const int wn = (wid & 3) * 32;        // 0 / 32 / 64 / 96

    // loader indices
    const int am = tid >> 2;              // 0..63
    const int ak = (tid & 3) * 8;         // 0,8,16,24
    const int bk = tid >> 3;              // 0..31
    const int bn = (tid & 7) * 16;        // 0..112

    const bool k_vec = ((K & 3) == 0);
    const int nkt = (K + BKK - 1) / BKK;

    float acc[2][4][4] = {};
    float ar[8], br[16];

    #define LOAD_TILE(KT)                                                      \
    {                                                                          \
        const int k0 = (KT) * BKK;                                             \
        const int gm = m0 + am;                                                \
        _Pragma("unroll") for (int i = 0; i < 8; i++) ar[i] = 0.f;             \
        if (gm < M) {                                                          \
            if (k_vec && (k0 + ak + 7 < K)) {                                  \
                const float4 a0 = *(const float4*)(A + (long)gm * K + k0 + ak);     \
                const float4 a1 = *(const float4*)(A + (long)gm * K + k0 + ak + 4); \
                ar[0]=a0.x; ar[1]=a0.y; ar[2]=a0.z; ar[3]=a0.w;                \
                ar[4]=a1.x; ar[5]=a1.y; ar[6]=a1.z; ar[7]=a1.w;                \
            } else {                                                           \
                _Pragma("unroll") for (int i = 0; i < 8; i++) {                \
                    const int gk = k0 + ak + i;                                \
                    if (gk < K) ar[i] = A[(long)gm * K + gk];                  \
                }                                                              \
            }                                                                  \
        }                                                                      \
        const int gk = k0 + bk;                                                \
        if (gk < K) {                                                          \
            const float* p = Bb + (long)gk * NN + n0 + bn;                     \
            _Pragma("unroll") for (int t = 0; t < 4; t++) {                    \
                const float4 v = *(const float4*)(p + 4 * t);                  \
                br[4*t]=v.x; br[4*t+1]=v.y; br[4*t+2]=v.z; br[4*t+3]=v.w;      \
            }                                                                  \
            if (B2b) {                                                         \
                const float* q = B2b + (long)gk * NN + n0 + bn;                \
                _Pragma("unroll") for (int t = 0; t < 4; t++) {                \
                    const float4 w = *(const float4*)(q + 4 * t);              \
                    br[4*t]+=w.x; br[4*t+1]+=w.y; br[4*t+2]+=w.z; br[4*t+3]+=w.w; \
                }                                                              \
            }                                                                  \
        } else {                                                               \
            _Pragma("unroll") for (int i = 0; i < 16; i++) br[i] = 0.f;        \
        }                                                                      \
    }

    #define STORE_TILE(BUF)                                                    \
    {                                                                          \
        __half ha[8];                                                          \
        _Pragma("unroll") for (int i = 0; i < 8; i++) ha[i] = __float2half_rn(ar[i]); \
        *(uint4*)&As[BUF][am][ak] = *(uint4*)&ha[0];                           \
        __half hb[16];                                                         \
        _Pragma("unroll") for (int i = 0; i < 16; i++) hb[i] = __float2half_rn(br[i]); \
        *(uint4*)&Bs[BUF][bk][bn]     = *(uint4*)&hb[0];                       \
        *(uint4*)&Bs[BUF][bk][bn + 8] = *(uint4*)&hb[8];                       \
    }

    LOAD_TILE(0)
    STORE_TILE(0)
    __syncthreads();

    for (int kt = 0; kt < nkt; kt++) {
        const int buf = kt & 1;
        const bool more = (kt + 1 < nkt);
        if (more) LOAD_TILE(kt + 1)

        #pragma unroll
        for (int ks = 0; ks < BKK; ks += 16) {
            unsigned afr[2][4], bfr[2][4];
            #pragma unroll
            for (int mi = 0; mi < 2; mi++) {
                const unsigned addr = smem_u32(
                    &As[buf][wm + mi * 16 + (lane & 15)][ks + (lane >> 4) * 8]);
                ldsm4(afr[mi], addr);
            }
            #pragma unroll
            for (int g = 0; g < 2; g++) {
                const int row = ks + (lane & 15);
                const int col = wn + g * 16 + ((lane >> 4) * 8);
                ldsm4t(bfr[g], smem_u32(&Bs[buf][row][col]));
            }
            #pragma unroll
            for (int mi = 0; mi < 2; mi++)
                #pragma unroll
                for (int g = 0; g < 2; g++) {
                    mma16816(acc[mi][2 * g],     afr[mi], bfr[g][0], bfr[g][1]);
                    mma16816(acc[mi][2 * g + 1], afr[mi], bfr[g][2], bfr[g][3]);
                }
        }
        if (more) {
            STORE_TILE(buf ^ 1)
            __syncthreads();
        }
    }

    // epilogue: c-frag (m16n8.f32): reg0/1 -> (row, col..col+1), reg2/3 -> row+8
    #pragma unroll
    for (int mi = 0; mi < 2; mi++) {
        #pragma unroll
        for (int hh = 0; hh < 2; hh++) {
            const int m = m0 + wm + mi * 16 + (lane >> 2) + hh * 8;
            if (m >= M) continue;
            const float scl = sc[m], bia = bi[m];
            #pragma unroll
            for (int ni = 0; ni < 4; ni++) {
                float v0 = acc[mi][ni][2 * hh]     * scl + bia;
                float v1 = acc[mi][ni][2 * hh + 1] * scl + bia;
                if (epi == 1) {
                    v0 = v0 / (1.f + __expf(-v0));
                    v1 = v1 / (1.f + __expf(-v1));
                }
                const int n = n0 + wn + ni * 8 + (lane & 3) * 2;
                const long base = (long)m * NN + n;
                if (Rb) {
                    const float2 r = *(const float2*)(Rb + base);
                    v0 += r.x; v1 += r.y;
                }
                *(float2*)(Cb + base) = make_float2(v0, v1);
            }
        }
    }
    #undef LOAD_TILE
    #undef STORE_TILE
}

// ---------------- depthwise 3x3 ----------------------------------------------
__global__ void dwconv_kernel(const float* __restrict__ w_pe,
                              const float* __restrict__ s,
                              const float* __restrict__ bi)
{
    const int bc = blockIdx.y;
    const int b = bc >> 8, c = bc & 255;
    const int hw = blockIdx.x * 256 + threadIdx.x;
    const int h = hw >> 6, w = hw & 63;
    const float* src = g_qkv + (long)b * QKV_BSTRIDE + (long)(512 + c) * NN;
    float acc = 0.f;
    #pragma unroll
    for (int kh = 0; kh < 3; kh++) {
        const int hh = h + kh - 1;
        if (hh < 0 || hh >= 64) continue;
        #pragma unroll
        for (int kw = 0; kw < 3; kw++) {
            const int ww = w + kw - 1;
            if (ww < 0 || ww >= 64) continue;
            acc += src[hh * 64 + ww] * w_pe[c * 9 + kh * 3 + kw];
        }
    }
    g_pe[(long)b * C_BSTRIDE + (long)c * NN + hw] = acc * s[c] + bi[c];
}

// ---- area attention: R5 shape (256 thr, 2 q/thread) — best measured (233us) --
// Reshape mapping verified in R1 (rel_err 2.7e-8):
//   q/k: addr = (f>>21)*QKV_BSTRIDE + (f&(2^21-1)), f = ba*2^19 + cc*1024 + n'
//   v:   addr = (f>>20)*QKV_BSTRIDE + 512*NN + (f&(2^20-1))
// softmax without max-subtraction is fp32-exact for these magnitudes.
#define BK 128
#define KROW 36   // 144 B rows: 16B-aligned for LDS.128

__global__ __launch_bounds__(256)
void attn_kernel()
{
    __shared__ __align__(16) float ks[BK][KROW];
    __shared__ __align__(16) float vs[BK][KROW];

    const int ba = blockIdx.y >> 3;
    const int h  = blockIdx.y & 7;
    const int q0 = blockIdx.x * 512;
    const int j  = threadIdx.x;
    const int nq0 = q0 + j;
    const int nq1 = q0 + j + 256;

    // 1/sqrt(32) * log2(e)  (exp via ex2)
    const float scale = 0.17677669529663687f * 1.4426950408889634f;

    const long qflat0 = (long)ba * 524288 + (long)(h * HD) * 1024;
    const long kflat0 = qflat0 + 256 * 1024;
    const long vflat0 = (long)ba * 262144 + (long)(h * HD) * 1024;

    unsigned long long qa[16], qb[16], oa[16], ob[16];
    #pragma unroll
    for (int d2 = 0; d2 < 16; d2++) {
        const long f0 = qflat0 + (long)(2 * d2) * 1024;
        const long f1 = f0 + 1024;
        const long g0 = f0 + nq0, g1 = f1 + nq0;
        const float a0 = g_qkv[(g0 >> 21) * QKV_BSTRIDE + (g0 & 2097151)] * scale;
        const float a1 = g_qkv[(g1 >> 21) * QKV_BSTRIDE + (g1 & 2097151)] * scale;
        qa[d2] = pk2(a0, a1);
        const long e0 = f0 + nq1, e1 = f1 + nq1;
        const float b0 = g_qkv[(e0 >> 21) * QKV_BSTRIDE + (e0 & 2097151)] * scale;
        const float b1 = g_qkv[(e1 >> 21) * QKV_BSTRIDE + (e1 & 2097151)] * scale;
        qb[d2] = pk2(b0, b1);
        oa[d2] = 0ull; ob[d2] = 0ull;
    }
    float lia = 0.f, lib = 0.f;

    for (int m0 = 0; m0 < NA; m0 += BK) {
        #pragma unroll
        for (int r = 0; r < 4; r++) {
            const int idx = r * 256 + j;          // 0..1023
            const int d = idx >> 5, m4 = (idx & 31) * 4;
            const long fk = kflat0 + (long)d * 1024 + m0 + m4;
            const float4 kv = *(const float4*)&g_qkv[(fk >> 21) * QKV_BSTRIDE + (fk & 2097151)];
            ks[m4 + 0][d] = kv.x; ks[m4 + 1][d] = kv.y;
            ks[m4 + 2][d] = kv.z; ks[m4 + 3][d] = kv.w;
            const long fv = vflat0 + (long)d * 1024 + m0 + m4;
            const float4 vv = *(const float4*)&g_qkv[(fv >> 20) * QKV_BSTRIDE + 512 * NN + (fv & 1048575)];
            vs[m4 + 0][d] = vv.x; vs[m4 + 1][d] = vv.y;
            vs[m4 + 2][d] = vv.z; vs[m4 + 3][d] = vv.w;
        }
        __syncthreads();
        #pragma unroll 2
        for (int m = 0; m < BK; m++) {
            unsigned long long sa0 = 0ull, sa1 = 0ull, sb0 = 0ull, sb1 = 0ull;
            const ulonglong2* kr = (const ulonglong2*)&ks[m][0];
            #pragma unroll
            for (int t = 0; t < 8; t++) {
                const ulonglong2 kk2 = kr[t];
                ffma2(sa0, qa[2 * t],     kk2.x, sa0);
                ffma2(sa1, qa[2 * t + 1], kk2.y, sa1);
                ffma2(sb0, qb[2 * t],     kk2.x, sb0);
                ffma2(sb1, qb[2 * t + 1], kk2.y, sb1);
            }
            unsigned long long sa, sb;
            fadd2(sa, sa0, sa1);
            fadd2(sb, sb0, sb1);
            const float2 fa = upk2(sa), fb = upk2(sb);
            const float pa = ex2(fa.x + fa.y);
            const float pb = ex2(fb.x + fb.y);
            lia += pa; lib += pb;
            const unsigned long long pa2 = pk2(pa, pa);
            const unsigned long long pb2 = pk2(pb, pb);
            const ulonglong2* vr = (const ulonglong2*)&vs[m][0];
            #pragma unroll
            for (int t = 0; t < 8; t++) {
                const ulonglong2 vv = vr[t];
                ffma2(oa[2 * t],     pa2, vv.x, oa[2 * t]);
                ffma2(oa[2 * t + 1], pa2, vv.y, oa[2 * t + 1]);
                ffma2(ob[2 * t],     pb2, vv.x, ob[2 * t]);
                ffma2(ob[2 * t + 1], pb2, vv.y, ob[2 * t + 1]);
            }
        }
        __syncthreads();
    }

    const float inva = 1.f / lia, invb = 1.f / lib;
    #pragma unroll
    for (int d2 = 0; d2 < 16; d2++) {
        const float2 va = upk2(oa[d2]);
        const float2 vb = upk2(ob[d2]);
        const long f0 = vflat0 + (long)(2 * d2) * 1024;
        const long f1 = f0 + 1024;
        const long g0 = f0 + nq0, g1 = f1 + nq0;
        g_att[(g0 >> 20) * C_BSTRIDE + (g0 & 1048575)] = va.x * inva;
        g_att[(g1 >> 20) * C_BSTRIDE + (g1 & 1048575)] = va.y * inva;
        const long e0 = f0 + nq1, e1 = f1 + nq1;
        g_att[(e0 >> 20) * C_BSTRIDE + (e0 & 1048575)] = vb.x * invb;
        g_att[(e1 >> 20) * C_BSTRIDE + (e1 & 1048575)] = vb.y * invb;
    }
}

// ---------------- launch -------------------------------------------------------
extern "C" void kernel_launch(void* const* d_in, const int* in_sizes, int n_in,
                              void* d_out, int out_size)
{
    const float* x      = (const float*)d_in[0];
    const float* w_qk   = (const float*)d_in[1];
    const float* s_qk   = (const float*)d_in[2];
    const float* b_qk   = (const float*)d_in[3];
    const float* w_v    = (const float*)d_in[4];
    const float* s_v    = (const float*)d_in[5];
    const float* b_v    = (const float*)d_in[6];
    const float* w_pe   = (const float*)d_in[7];
    const float* s_pe   = (const float*)d_in[8];
    const float* b_pe   = (const float*)d_in[9];
    const float* w_proj = (const float*)d_in[10];
    const float* s_proj = (const float*)d_in[11];
    const float* b_proj = (const float*)d_in[12];
    const float* w_m1   = (const float*)d_in[13];
    const float* s_m1   = (const float*)d_in[14];
    const float* b_m1   = (const float*)d_in[15];
    const float* w_m2   = (const float*)d_in[16];
    const float* s_m2   = (const float*)d_in[17];
    const float* b_m2   = (const float*)d_in[18];
    float* out = (float*)d_out;

    float *qkv, *pe, *att, *x1, *mb;
    cudaGetSymbolAddress((void**)&qkv, g_qkv);
    cudaGetSymbolAddress((void**)&pe,  g_pe);
    cudaGetSymbolAddress((void**)&att, g_att);
    cudaGetSymbolAddress((void**)&x1,  g_x1);
    cudaGetSymbolAddress((void**)&mb,  g_m);

    // qk -> g_qkv channels [0,512)   (M=512 -> 8 m-blocks)
    gemm_kernel<<<dim3(32, 8, BSZ), 256>>>(w_qk, x, nullptr, s_qk, b_qk, nullptr,
        qkv, 512, 256, (long)C_BSTRIDE, (long)QKV_BSTRIDE, 0, 0);
    // v -> g_qkv channels [512,768)  (M=256 -> 4)
    gemm_kernel<<<dim3(32, 4, BSZ), 256>>>(w_v, x, nullptr, s_v, b_v, nullptr,
        qkv + 512 * NN, 256, 256, (long)C_BSTRIDE, (long)QKV_BSTRIDE, 0, 0);
    // pe = dwconv3x3(v)
    dwconv_kernel<<<dim3(16, BSZ * CC), 256>>>(w_pe, s_pe, b_pe);
    // area attention -> g_att
    attn_kernel<<<dim3(NA / 512, BA * HEADS), 256>>>();
    // x1 = x + conv1x1(att + pe, w_proj)
    gemm_kernel<<<dim3(32, 4, BSZ), 256>>>(w_proj, att, pe, s_proj, b_proj, x,
        x1, 256, 256, (long)C_BSTRIDE, (long)C_BSTRIDE, (long)C_BSTRIDE, 0);
    // m = silu(conv1x1(x1, w_m1))    (M=307 -> 5)
    gemm_kernel<<<dim3(32, 5, BSZ), 256>>>(w_m1, x1, nullptr, s_m1, b_m1, nullptr,
        mb, MLPD, 256, (long)C_BSTRIDE, (long)MLPD * NN, 0, 1);
    // out = x1 + conv1x1(m, w_m2)    (K=307)
    gemm_kernel<<<dim3(32, 4, BSZ), 256>>>(w_m2, mb, nullptr, s_m2, b_m2, x1,
        out, 256, MLPD, (long)MLPD * NN, (long)C_BSTRIDE, (long)C_BSTRIDE, 0);
}

// round 11
// speedup vs baseline: 3.5336x; 2.0641x over previous
#include <cuda_runtime.h>
#include <cuda_fp16.h>
#include <math.h>

// Problem constants
#define BSZ   2
#define CC    256
#define NN    4096          // H*W
#define HEADS 8
#define HD    32
#define BA    8             // BSZ*AREA
#define NA    1024          // NN/AREA
#define MLPD  307

#define QKV_BSTRIDE (768*NN)
#define C_BSTRIDE   (CC*NN)

// ---------------- scratch ----------------------------------------------------
__device__ float g_qkv[BSZ * 768 * NN];
__device__ float g_pe [BSZ * CC  * NN];
__device__ float g_att[BSZ * CC  * NN];
__device__ float g_x1 [BSZ * CC  * NN];
__device__ float g_m  [BSZ * MLPD* NN];

// ---------------- helpers -----------------------------------------------------
__device__ __forceinline__ float ex2(float x) {
    float r;
    asm("ex2.approx.ftz.f32 %0, %1;" : "=f"(r) : "f"(x));
    return r;
}
__device__ __forceinline__ unsigned smem_u32(const void* p) {
    return (unsigned)__cvta_generic_to_shared(p);
}
__device__ __forceinline__ void ldsm4(unsigned* r, unsigned addr) {
    asm volatile("ldmatrix.sync.aligned.m8n8.x4.shared.b16 {%0,%1,%2,%3}, [%4];"
        : "=r"(r[0]), "=r"(r[1]), "=r"(r[2]), "=r"(r[3]) : "r"(addr));
}
__device__ __forceinline__ void ldsm4t(unsigned* r, unsigned addr) {
    asm volatile("ldmatrix.sync.aligned.m8n8.x4.trans.shared.b16 {%0,%1,%2,%3}, [%4];"
        : "=r"(r[0]), "=r"(r[1]), "=r"(r[2]), "=r"(r[3]) : "r"(addr));
}
__device__ __forceinline__ void mma16816(float* c, const unsigned* a,
                                         unsigned b0, unsigned b1) {
    asm volatile("mma.sync.aligned.m16n8k16.row.col.f32.f16.f16.f32 "
        "{%0,%1,%2,%3},{%4,%5,%6,%7},{%8,%9},{%0,%1,%2,%3};"
        : "+f"(c[0]), "+f"(c[1]), "+f"(c[2]), "+f"(c[3])
        : "r"(a[0]), "r"(a[1]), "r"(a[2]), "r"(a[3]), "r"(b0), "r"(b1));
}
__device__ __forceinline__ unsigned pkh2(float a, float b) {
    __half2 h = __floats2half2_rn(a, b);
    return *(unsigned*)&h;
}

// ---- conv1x1 GEMM via HMMA (fp16 in, fp32 acc): 64m x 128n, 8 warps ---------
// (identical to R10 — verified, ~95us aggregate)
#define BKK 32
#define AP  (BKK + 8)
#define BP  (128 + 8)

__global__ __launch_bounds__(256)
void gemm_kernel(const float* __restrict__ A,
                 const float* __restrict__ Bm,
                 const float* __restrict__ B2,
                 const float* __restrict__ sc,
                 const float* __restrict__ bi,
                 const float* __restrict__ res,
                 float* __restrict__ Cout,
                 int M, int K,
                 long sB, long sC, long sR, int epi)
{
    __shared__ __align__(16) __half As[2][64][AP];
    __shared__ __align__(16) __half Bs[2][BKK][BP];

    const int b = blockIdx.z;
    const float* Bb  = Bm + (long)b * sB;
    const float* B2b = B2 ? (B2 + (long)b * sB) : nullptr;
    const float* Rb  = res ? (res + (long)b * sR) : nullptr;
    float* Cb = Cout + (long)b * sC;

    const int m0 = blockIdx.y * 64;
    const int n0 = blockIdx.x * 128;
    const int tid  = threadIdx.x;
    const int lane = tid & 31;
    const int wid  = tid >> 5;
    const int wm = (wid >> 2) * 32;
    const int wn = (wid & 3) * 32;

    const int am = tid >> 2;
    const int ak = (tid & 3) * 8;
    const int bk = tid >> 3;
    const int bn = (tid & 7) * 16;

    const bool k_vec = ((K & 3) == 0);
    const int nkt = (K + BKK - 1) / BKK;

    float acc[2][4][4] = {};
    float ar[8], br[16];

    #define LOAD_TILE(KT)                                                      \
    {                                                                          \
        const int k0 = (KT) * BKK;                                             \
        const int gm = m0 + am;                                                \
        _Pragma("unroll") for (int i = 0; i < 8; i++) ar[i] = 0.f;             \
        if (gm < M) {                                                          \
            if (k_vec && (k0 + ak + 7 < K)) {                                  \
                const float4 a0 = *(const float4*)(A + (long)gm * K + k0 + ak);     \
                const float4 a1 = *(const float4*)(A + (long)gm * K + k0 + ak + 4); \
                ar[0]=a0.x; ar[1]=a0.y; ar[2]=a0.z; ar[3]=a0.w;                \
                ar[4]=a1.x; ar[5]=a1.y; ar[6]=a1.z; ar[7]=a1.w;                \
            } else {                                                           \
                _Pragma("unroll") for (int i = 0; i < 8; i++) {                \
                    const int gk = k0 + ak + i;                                \
                    if (gk < K) ar[i] = A[(long)gm * K + gk];                  \
                }                                                              \
            }                                                                  \
        }                                                                      \
        const int gk = k0 + bk;                                                \
        if (gk < K) {                                                          \
            const float* p = Bb + (long)gk * NN + n0 + bn;                     \
            _Pragma("unroll") for (int t = 0; t < 4; t++) {                    \
                const float4 v = *(const float4*)(p + 4 * t);                  \
                br[4*t]=v.x; br[4*t+1]=v.y; br[4*t+2]=v.z; br[4*t+3]=v.w;      \
            }                                                                  \
            if (B2b) {                                                         \
                const float* q = B2b + (long)gk * NN + n0 + bn;                \
                _Pragma("unroll") for (int t = 0; t < 4; t++) {                \
                    const float4 w = *(const float4*)(q + 4 * t);              \
                    br[4*t]+=w.x; br[4*t+1]+=w.y; br[4*t+2]+=w.z; br[4*t+3]+=w.w; \
                }                                                              \
            }                                                                  \
        } else {                                                               \
            _Pragma("unroll") for (int i = 0; i < 16; i++) br[i] = 0.f;        \
        }                                                                      \
    }

    #define STORE_TILE(BUF)                                                    \
    {                                                                          \
        __half ha[8];                                                          \
        _Pragma("unroll") for (int i = 0; i < 8; i++) ha[i] = __float2half_rn(ar[i]); \
        *(uint4*)&As[BUF][am][ak] = *(uint4*)&ha[0];                           \
        __half hb[16];                                                         \
        _Pragma("unroll") for (int i = 0; i < 16; i++) hb[i] = __float2half_rn(br[i]); \
        *(uint4*)&Bs[BUF][bk][bn]     = *(uint4*)&hb[0];                       \
        *(uint4*)&Bs[BUF][bk][bn + 8] = *(uint4*)&hb[8];                       \
    }

    LOAD_TILE(0)
    STORE_TILE(0)
    __syncthreads();

    for (int kt = 0; kt < nkt; kt++) {
        const int buf = kt & 1;
        const bool more = (kt + 1 < nkt);
        if (more) LOAD_TILE(kt + 1)

        #pragma unroll
        for (int ks = 0; ks < BKK; ks += 16) {
            unsigned afr[2][4], bfr[2][4];
            #pragma unroll
            for (int mi = 0; mi < 2; mi++) {
                const unsigned addr = smem_u32(
                    &As[buf][wm + mi * 16 + (lane & 15)][ks + (lane >> 4) * 8]);
                ldsm4(afr[mi], addr);
            }
            #pragma unroll
            for (int g = 0; g < 2; g++) {
                const int row = ks + (lane & 15);
                const int col = wn + g * 16 + ((lane >> 4) * 8);
                ldsm4t(bfr[g], smem_u32(&Bs[buf][row][col]));
            }
            #pragma unroll
            for (int mi = 0; mi < 2; mi++)
                #pragma unroll
                for (int g = 0; g < 2; g++) {
                    mma16816(acc[mi][2 * g],     afr[mi], bfr[g][0], bfr[g][1]);
                    mma16816(acc[mi][2 * g + 1], afr[mi], bfr[g][2], bfr[g][3]);
                }
        }
        if (more) {
            STORE_TILE(buf ^ 1)
            __syncthreads();
        }
    }

    #pragma unroll
    for (int mi = 0; mi < 2; mi++) {
        #pragma unroll
        for (int hh = 0; hh < 2; hh++) {
            const int m = m0 + wm + mi * 16 + (lane >> 2) + hh * 8;
            if (m >= M) continue;
            const float scl = sc[m], bia = bi[m];
            #pragma unroll
            for (int ni = 0; ni < 4; ni++) {
                float v0 = acc[mi][ni][2 * hh]     * scl + bia;
                float v1 = acc[mi][ni][2 * hh + 1] * scl + bia;
                if (epi == 1) {
                    v0 = v0 / (1.f + __expf(-v0));
                    v1 = v1 / (1.f + __expf(-v1));
                }
                const int n = n0 + wn + ni * 8 + (lane & 3) * 2;
                const long base = (long)m * NN + n;
                if (Rb) {
                    const float2 r = *(const float2*)(Rb + base);
                    v0 += r.x; v1 += r.y;
                }
                *(float2*)(Cb + base) = make_float2(v0, v1);
            }
        }
    }
    #undef LOAD_TILE
    #undef STORE_TILE
}

// ---------------- depthwise 3x3 ----------------------------------------------
__global__ void dwconv_kernel(const float* __restrict__ w_pe,
                              const float* __restrict__ s,
                              const float* __restrict__ bi)
{
    const int bc = blockIdx.y;
    const int b = bc >> 8, c = bc & 255;
    const int hw = blockIdx.x * 256 + threadIdx.x;
    const int h = hw >> 6, w = hw & 63;
    const float* src = g_qkv + (long)b * QKV_BSTRIDE + (long)(512 + c) * NN;
    float acc = 0.f;
    #pragma unroll
    for (int kh = 0; kh < 3; kh++) {
        const int hh = h + kh - 1;
        if (hh < 0 || hh >= 64) continue;
        #pragma unroll
        for (int kw = 0; kw < 3; kw++) {
            const int ww = w + kw - 1;
            if (ww < 0 || ww >= 64) continue;
            acc += src[hh * 64 + ww] * w_pe[c * 9 + kh * 3 + kw];
        }
    }
    g_pe[(long)b * C_BSTRIDE + (long)c * NN + hw] = acc * s[c] + bi[c];
}

// ---- area attention via HMMA -------------------------------------------------
// q/k/v rows are d-major [32][1024] in g_qkv (flat mapping verified R1).
// Smem tiles stay d-major [32][128]: Q a-frags + K b-frags via ldmatrix.trans,
// V b-frags via plain ldmatrix — no transposes anywhere.
// S c-frag (2 adjacent n8 tiles) == P a-frag layout (flash-attention identity).
// scale*log2e folded into Q; exp via ex2; softmax w/o max-sub (fp32-safe here).
#define PITCH 136    // halves per smem row (272B: 16B-divisible, bank-clean)

__global__ __launch_bounds__(256)
void attn_kernel()
{
    __shared__ __align__(16) __half Qs[32][PITCH];
    __shared__ __align__(16) __half Ks[32][PITCH];
    __shared__ __align__(16) __half Vs[32][PITCH];

    const int ba = blockIdx.y >> 3;
    const int h  = blockIdx.y & 7;
    const int q0 = blockIdx.x * 128;
    const int tid  = threadIdx.x;
    const int lane = tid & 31;
    const int wid  = tid >> 5;
    const int wq   = wid * 16;          // warp's 16 queries within the 128 tile

    const float scale = 0.17677669529663687f * 1.4426950408889634f;

    const long qflat0 = (long)ba * 524288 + (long)(h * HD) * 1024;
    const long kflat0 = qflat0 + 256 * 1024;
    const long vflat0 = (long)ba * 262144 + (long)(h * HD) * 1024;

    // fill mapping: d = tid>>3 (0..31), 16 contiguous cols at (tid&7)*16
    const int fd = tid >> 3;
    const int fg = (tid & 7) * 16;

    // ---- Q tile fill (once, scaled) ----
    {
        const long f = qflat0 + (long)fd * 1024 + q0 + fg;
        const float* src = &g_qkv[(f >> 21) * QKV_BSTRIDE + (f & 2097151)];
        __half t[16];
        #pragma unroll
        for (int i = 0; i < 4; i++) {
            const float4 v = *(const float4*)(src + 4 * i);
            t[4*i+0] = __float2half_rn(v.x * scale);
            t[4*i+1] = __float2half_rn(v.y * scale);
            t[4*i+2] = __float2half_rn(v.z * scale);
            t[4*i+3] = __float2half_rn(v.w * scale);
        }
        *(uint4*)&Qs[fd][fg]     = *(uint4*)&t[0];
        *(uint4*)&Qs[fd][fg + 8] = *(uint4*)&t[8];
    }
    __syncthreads();

    // Q a-frags (m16k16, two d-chunks), via ldmatrix.trans on d-major tile
    unsigned aq[2][4];
    #pragma unroll
    for (int dc = 0; dc < 2; dc++) {
        const int row = dc * 16 + (lane & 7) + ((lane >> 4) & 1) * 8;
        const int col = wq + ((lane >> 3) & 1) * 8;
        ldsm4t(aq[dc], smem_u32(&Qs[row][col]));
    }

    float oacc[4][4] = {};
    float lsum0 = 0.f, lsum1 = 0.f;

    for (int m0 = 0; m0 < NA; m0 += 128) {
        __syncthreads();   // prior chunk's ldmatrix reads done
        // K/V tile fill (vectorized, conflict-free)
        {
            const long fk = kflat0 + (long)fd * 1024 + m0 + fg;
            const float* sk = &g_qkv[(fk >> 21) * QKV_BSTRIDE + (fk & 2097151)];
            __half t[16];
            #pragma unroll
            for (int i = 0; i < 4; i++) {
                const float4 v = *(const float4*)(sk + 4 * i);
                t[4*i+0] = __float2half_rn(v.x);
                t[4*i+1] = __float2half_rn(v.y);
                t[4*i+2] = __float2half_rn(v.z);
                t[4*i+3] = __float2half_rn(v.w);
            }
            *(uint4*)&Ks[fd][fg]     = *(uint4*)&t[0];
            *(uint4*)&Ks[fd][fg + 8] = *(uint4*)&t[8];

            const long fv = vflat0 + (long)fd * 1024 + m0 + fg;
            const float* sv = &g_qkv[(fv >> 20) * QKV_BSTRIDE + 512 * NN + (fv & 1048575)];
            #pragma unroll
            for (int i = 0; i < 4; i++) {
                const float4 v = *(const float4*)(sv + 4 * i);
                t[4*i+0] = __float2half_rn(v.x);
                t[4*i+1] = __float2half_rn(v.y);
                t[4*i+2] = __float2half_rn(v.z);
                t[4*i+3] = __float2half_rn(v.w);
            }
            *(uint4*)&Vs[fd][fg]     = *(uint4*)&t[0];
            *(uint4*)&Vs[fd][fg + 8] = *(uint4*)&t[8];
        }
        __syncthreads();

        // ---- S = Q^T K : 16 key-n8-tiles x m16, f32 accum ----
        float sacc[16][4];
        #pragma unroll
        for (int nt = 0; nt < 16; nt++) {
            sacc[nt][0] = 0.f; sacc[nt][1] = 0.f;
            sacc[nt][2] = 0.f; sacc[nt][3] = 0.f;
        }
        #pragma unroll
        for (int dc = 0; dc < 2; dc++) {
            #pragma unroll
            for (int ntp = 0; ntp < 8; ntp++) {
                unsigned bk[4];
                const int row = dc * 16 + (lane & 7) + ((lane >> 3) & 1) * 8;
                const int col = ntp * 16 + ((lane >> 4) & 1) * 8;
                ldsm4t(bk, smem_u32(&Ks[row][col]));
                mma16816(sacc[2 * ntp],     aq[dc], bk[0], bk[1]);
                mma16816(sacc[2 * ntp + 1], aq[dc], bk[2], bk[3]);
            }
        }
        // ---- exp (log2 domain) + li ----
        #pragma unroll
        for (int nt = 0; nt < 16; nt++) {
            sacc[nt][0] = ex2(sacc[nt][0]);
            sacc[nt][1] = ex2(sacc[nt][1]);
            sacc[nt][2] = ex2(sacc[nt][2]);
            sacc[nt][3] = ex2(sacc[nt][3]);
            lsum0 += sacc[nt][0] + sacc[nt][1];
            lsum1 += sacc[nt][2] + sacc[nt][3];
        }
        // ---- out += P V^T : P c-frag pairs -> a-frags ----
        #pragma unroll
        for (int kt = 0; kt < 8; kt++) {
            unsigned pa[4];
            pa[0] = pkh2(sacc[2 * kt][0],     sacc[2 * kt][1]);
            pa[1] = pkh2(sacc[2 * kt][2],     sacc[2 * kt][3]);
            pa[2] = pkh2(sacc[2 * kt + 1][0], sacc[2 * kt + 1][1]);
            pa[3] = pkh2(sacc[2 * kt + 1][2], sacc[2 * kt + 1][3]);
            #pragma unroll
            for (int dtp = 0; dtp < 2; dtp++) {
                unsigned bv[4];
                const int row = dtp * 16 + (lane & 7) + ((lane >> 4) & 1) * 8;
                const int col = kt * 16 + ((lane >> 3) & 1) * 8;
                ldsm4(bv, smem_u32(&Vs[row][col]));
                mma16816(oacc[2 * dtp],     pa, bv[0], bv[1]);
                mma16816(oacc[2 * dtp + 1], pa, bv[2], bv[3]);
            }
        }
    }

    // li reduce across the quad owning each row
    lsum0 += __shfl_xor_sync(0xffffffff, lsum0, 1);
    lsum0 += __shfl_xor_sync(0xffffffff, lsum0, 2);
    lsum1 += __shfl_xor_sync(0xffffffff, lsum1, 1);
    lsum1 += __shfl_xor_sync(0xffffffff, lsum1, 2);
    const float inv0 = 1.f / lsum0;
    const float inv1 = 1.f / lsum1;

    // write out: c-frag rows (lane>>2, +8), cols d = dt*8 + (lane&3)*2
    const int qg = q0 + wq + (lane >> 2);
    #pragma unroll
    for (int dt = 0; dt < 4; dt++) {
        const int d = dt * 8 + (lane & 3) * 2;
        #pragma unroll
        for (int e = 0; e < 2; e++) {
            const long f0 = vflat0 + (long)(d + e) * 1024 + qg;
            g_att[(f0 >> 20) * C_BSTRIDE + (f0 & 1048575)] = oacc[dt][e] * inv0;
            const long f1 = f0 + 8;   // query row +8
            g_att[(f1 >> 20) * C_BSTRIDE + (f1 & 1048575)] = oacc[dt][2 + e] * inv1;
        }
    }
}

// ---------------- launch -------------------------------------------------------
extern "C" void kernel_launch(void* const* d_in, const int* in_sizes, int n_in,
                              void* d_out, int out_size)
{
    const float* x      = (const float*)d_in[0];
    const float* w_qk   = (const float*)d_in[1];
    const float* s_qk   = (const float*)d_in[2];
    const float* b_qk   = (const float*)d_in[3];
    const float* w_v    = (const float*)d_in[4];
    const float* s_v    = (const float*)d_in[5];
    const float* b_v    = (const float*)d_in[6];
    const float* w_pe   = (const float*)d_in[7];
    const float* s_pe   = (const float*)d_in[8];
    const float* b_pe   = (const float*)d_in[9];
    const float* w_proj = (const float*)d_in[10];
    const float* s_proj = (const float*)d_in[11];
    const float* b_proj = (const float*)d_in[12];
    const float* w_m1   = (const float*)d_in[13];
    const float* s_m1   = (const float*)d_in[14];
    const float* b_m1   = (const float*)d_in[15];
    const float* w_m2   = (const float*)d_in[16];
    const float* s_m2   = (const float*)d_in[17];
    const float* b_m2   = (const float*)d_in[18];
    float* out = (float*)d_out;

    float *qkv, *pe, *att, *x1, *mb;
    cudaGetSymbolAddress((void**)&qkv, g_qkv);
    cudaGetSymbolAddress((void**)&pe,  g_pe);
    cudaGetSymbolAddress((void**)&att, g_att);
    cudaGetSymbolAddress((void**)&x1,  g_x1);
    cudaGetSymbolAddress((void**)&mb,  g_m);

    // qk -> g_qkv channels [0,512)
    gemm_kernel<<<dim3(32, 8, BSZ), 256>>>(w_qk, x, nullptr, s_qk, b_qk, nullptr,
        qkv, 512, 256, (long)C_BSTRIDE, (long)QKV_BSTRIDE, 0, 0);
    // v -> g_qkv channels [512,768)
    gemm_kernel<<<dim3(32, 4, BSZ), 256>>>(w_v, x, nullptr, s_v, b_v, nullptr,
        qkv + 512 * NN, 256, 256, (long)C_BSTRIDE, (long)QKV_BSTRIDE, 0, 0);
    // pe = dwconv3x3(v)
    dwconv_kernel<<<dim3(16, BSZ * CC), 256>>>(w_pe, s_pe, b_pe);
    // area attention -> g_att : 8 q-blocks x 64 (ba,h)
    attn_kernel<<<dim3(NA / 128, BA * HEADS), 256>>>();
    // x1 = x + conv1x1(att + pe, w_proj)
    gemm_kernel<<<dim3(32, 4, BSZ), 256>>>(w_proj, att, pe, s_proj, b_proj, x,
        x1, 256, 256, (long)C_BSTRIDE, (long)C_BSTRIDE, (long)C_BSTRIDE, 0);
    // m = silu(conv1x1(x1, w_m1))
    gemm_kernel<<<dim3(32, 5, BSZ), 256>>>(w_m1, x1, nullptr, s_m1, b_m1, nullptr,
        mb, MLPD, 256, (long)C_BSTRIDE, (long)MLPD * NN, 0, 1);
    // out = x1 + conv1x1(m, w_m2)
    gemm_kernel<<<dim3(32, 4, BSZ), 256>>>(w_m2, mb, nullptr, s_m2, b_m2, x1,
        out, 256, MLPD, (long)MLPD * NN, (long)C_BSTRIDE, (long)C_BSTRIDE, 0);
}

// round 12
// speedup vs baseline: 3.5654x; 1.0090x over previous
#include <cuda_runtime.h>
#include <cuda_fp16.h>
#include <math.h>

// Problem constants
#define BSZ   2
#define CC    256
#define NN    4096          // H*W
#define HEADS 8
#define HD    32
#define BA    8             // BSZ*AREA
#define NA    1024          // NN/AREA
#define MLPD  307

#define QKV_BSTRIDE (768*NN)
#define C_BSTRIDE   (CC*NN)

// ---------------- scratch ----------------------------------------------------
__device__ float g_qkv[BSZ * 768 * NN];
__device__ float g_pe [BSZ * CC  * NN];
__device__ float g_att[BSZ * CC  * NN];
__device__ float g_x1 [BSZ * CC  * NN];
__device__ float g_m  [BSZ * MLPD* NN];

// ---------------- helpers -----------------------------------------------------
__device__ __forceinline__ float ex2(float x) {
    float r;
    asm("ex2.approx.ftz.f32 %0, %1;" : "=f"(r) : "f"(x));
    return r;
}
__device__ __forceinline__ unsigned smem_u32(const void* p) {
    return (unsigned)__cvta_generic_to_shared(p);
}
__device__ __forceinline__ void ldsm4(unsigned* r, unsigned addr) {
    asm volatile("ldmatrix.sync.aligned.m8n8.x4.shared.b16 {%0,%1,%2,%3}, [%4];"
        : "=r"(r[0]), "=r"(r[1]), "=r"(r[2]), "=r"(r[3]) : "r"(addr));
}
__device__ __forceinline__ void ldsm4t(unsigned* r, unsigned addr) {
    asm volatile("ldmatrix.sync.aligned.m8n8.x4.trans.shared.b16 {%0,%1,%2,%3}, [%4];"
        : "=r"(r[0]), "=r"(r[1]), "=r"(r[2]), "=r"(r[3]) : "r"(addr));
}
__device__ __forceinline__ void mma16816(float* c, const unsigned* a,
                                         unsigned b0, unsigned b1) {
    asm volatile("mma.sync.aligned.m16n8k16.row.col.f32.f16.f16.f32 "
        "{%0,%1,%2,%3},{%4,%5,%6,%7},{%8,%9},{%0,%1,%2,%3};"
        : "+f"(c[0]), "+f"(c[1]), "+f"(c[2]), "+f"(c[3])
        : "r"(a[0]), "r"(a[1]), "r"(a[2]), "r"(a[3]), "r"(b0), "r"(b1));
}
__device__ __forceinline__ unsigned pkh2(float a, float b) {
    __half2 h = __floats2half2_rn(a, b);
    return *(unsigned*)&h;
}

// ---- conv1x1 GEMM via HMMA: 128m x 128n CTA tile, 8 warps (64m x 32n each) --
// C[b][m][n] = epi((sum_k A[m][k]*(Bm[b][k][n](+B2))) * sc[m] + bi[m]) (+ res)
#define BKK 32
#define AP  (BKK + 8)      // As row pitch (halves)
#define BP  (128 + 8)      // Bs row pitch (halves)

__global__ __launch_bounds__(256, 2)
void gemm_kernel(const float* __restrict__ A,
                 const float* __restrict__ Bm,
                 const float* __restrict__ B2,
                 const float* __restrict__ sc,
                 const float* __restrict__ bi,
                 const float* __restrict__ res,
                 float* __restrict__ Cout,
                 int M, int K,
                 long sB, long sC, long sR, int epi)
{
    __shared__ __align__(16) __half As[2][128][AP];   // 20.5 KB
    __shared__ __align__(16) __half Bs[2][BKK][BP];   // 17.4 KB

    const int b = blockIdx.z;
    const float* Bb  = Bm + (long)b * sB;
    const float* B2b = B2 ? (B2 + (long)b * sB) : nullptr;
    const float* Rb  = res ? (res + (long)b * sR) : nullptr;
    float* Cb = Cout + (long)b * sC;

    const int m0 = blockIdx.y * 128;
    const int n0 = blockIdx.x * 128;
    const int tid  = threadIdx.x;
    const int lane = tid & 31;
    const int wid  = tid >> 5;
    const int wm = (wid >> 2) * 64;       // 0 / 64
    const int wn = (wid & 3) * 32;        // 0 / 32 / 64 / 96

    // loader indices
    const int am = tid >> 1;              // 0..127
    const int ak = (tid & 1) * 16;        // 0 or 16
    const int bk = tid >> 3;              // 0..31
    const int bn = (tid & 7) * 16;        // 0..112

    const bool k_vec = ((K & 3) == 0);
    const int nkt = (K + BKK - 1) / BKK;

    float acc[4][4][4] = {};              // mi x ni x frag
    uint4 apk[2], bpk[2];                 // fp16-packed prefetch

    #define LOAD_TILE(KT)                                                      \
    {                                                                          \
        const int k0 = (KT) * BKK;                                             \
        const int gm = m0 + am;                                                \
        float t[16];                                                           \
        _Pragma("unroll") for (int i = 0; i < 16; i++) t[i] = 0.f;             \
        if (gm < M) {                                                          \
            if (k_vec && (k0 + ak + 15 < K)) {                                 \
                _Pragma("unroll") for (int q4 = 0; q4 < 4; q4++) {             \
                    const float4 v = *(const float4*)(A + (long)gm * K + k0 + ak + 4 * q4); \
                    t[4*q4]=v.x; t[4*q4+1]=v.y; t[4*q4+2]=v.z; t[4*q4+3]=v.w;  \
                }                                                              \
            } else {                                                           \
                _Pragma("unroll") for (int i = 0; i < 16; i++) {               \
                    const int gk = k0 + ak + i;                                \
                    if (gk < K) t[i] = A[(long)gm * K + gk];                   \
                }                                                              \
            }                                                                  \
        }                                                                      \
        {                                                                      \
            __half h[16];                                                      \
            _Pragma("unroll") for (int i = 0; i < 16; i++) h[i] = __float2half_rn(t[i]); \
            apk[0] = *(uint4*)&h[0]; apk[1] = *(uint4*)&h[8];                  \
        }                                                                      \
        const int gk = k0 + bk;                                                \
        _Pragma("unroll") for (int i = 0; i < 16; i++) t[i] = 0.f;             \
        if (gk < K) {                                                          \
            const float* p = Bb + (long)gk * NN + n0 + bn;                     \
            _Pragma("unroll") for (int q4 = 0; q4 < 4; q4++) {                 \
                const float4 v = *(const float4*)(p + 4 * q4);                 \
                t[4*q4]=v.x; t[4*q4+1]=v.y; t[4*q4+2]=v.z; t[4*q4+3]=v.w;      \
            }                                                                  \
            if (B2b) {                                                         \
                const float* q = B2b + (long)gk * NN + n0 + bn;                \
                _Pragma("unroll") for (int q4 = 0; q4 < 4; q4++) {             \
                    const float4 w = *(const float4*)(q + 4 * q4);             \
                    t[4*q4]+=w.x; t[4*q4+1]+=w.y; t[4*q4+2]+=w.z; t[4*q4+3]+=w.w; \
                }                                                              \
            }                                                                  \
        }                                                                      \
        {                                                                      \
            __half h[16];                                                      \
            _Pragma("unroll") for (int i = 0; i < 16; i++) h[i] = __float2half_rn(t[i]); \
            bpk[0] = *(uint4*)&h[0]; bpk[1] = *(uint4*)&h[8];                  \
        }                                                                      \
    }

    #define STORE_TILE(BUF)                                                    \
    {                                                                          \
        *(uint4*)&As[BUF][am][ak]     = apk[0];                                \
        *(uint4*)&As[BUF][am][ak + 8] = apk[1];                                \
        *(uint4*)&Bs[BUF][bk][bn]     = bpk[0];                                \
        *(uint4*)&Bs[BUF][bk][bn + 8] = bpk[1];                                \
    }

    LOAD_TILE(0)
    STORE_TILE(0)
    __syncthreads();

    for (int kt = 0; kt < nkt; kt++) {
        const int buf = kt & 1;
        const bool more = (kt + 1 < nkt);
        if (more) LOAD_TILE(kt + 1)

        #pragma unroll
        for (int ks = 0; ks < BKK; ks += 16) {
            unsigned afr[4][4], bfr[2][4];
            #pragma unroll
            for (int mi = 0; mi < 4; mi++) {
                const unsigned addr = smem_u32(
                    &As[buf][wm + mi * 16 + (lane & 15)][ks + (lane >> 4) * 8]);
                ldsm4(afr[mi], addr);
            }
            #pragma unroll
            for (int g = 0; g < 2; g++) {
                const int row = ks + (lane & 15);
                const int col = wn + g * 16 + ((lane >> 4) * 8);
                ldsm4t(bfr[g], smem_u32(&Bs[buf][row][col]));
            }
            #pragma unroll
            for (int mi = 0; mi < 4; mi++)
                #pragma unroll
                for (int g = 0; g < 2; g++) {
                    mma16816(acc[mi][2 * g],     afr[mi], bfr[g][0], bfr[g][1]);
                    mma16816(acc[mi][2 * g + 1], afr[mi], bfr[g][2], bfr[g][3]);
                }
        }
        if (more) {
            STORE_TILE(buf ^ 1)
            __syncthreads();
        }
    }

    // epilogue: c-frag (m16n8.f32): regs 0/1 -> (row, col..col+1), 2/3 -> row+8
    #pragma unroll
    for (int mi = 0; mi < 4; mi++) {
        #pragma unroll
        for (int hh = 0; hh < 2; hh++) {
            const int m = m0 + wm + mi * 16 + (lane >> 2) + hh * 8;
            if (m >= M) continue;
            const float scl = sc[m], bia = bi[m];
            #pragma unroll
            for (int ni = 0; ni < 4; ni++) {
                float v0 = acc[mi][ni][2 * hh]     * scl + bia;
                float v1 = acc[mi][ni][2 * hh + 1] * scl + bia;
                if (epi == 1) {
                    v0 = v0 / (1.f + __expf(-v0));
                    v1 = v1 / (1.f + __expf(-v1));
                }
                const int n = n0 + wn + ni * 8 + (lane & 3) * 2;
                const long base = (long)m * NN + n;
                if (Rb) {
                    const float2 r = *(const float2*)(Rb + base);
                    v0 += r.x; v1 += r.y;
                }
                *(float2*)(Cb + base) = make_float2(v0, v1);
            }
        }
    }
    #undef LOAD_TILE
    #undef STORE_TILE
}

// ---------------- depthwise 3x3 ----------------------------------------------
__global__ void dwconv_kernel(const float* __restrict__ w_pe,
                              const float* __restrict__ s,
                              const float* __restrict__ bi)
{
    const int bc = blockIdx.y;
    const int b = bc >> 8, c = bc & 255;
    const int hw = blockIdx.x * 256 + threadIdx.x;
    const int h = hw >> 6, w = hw & 63;
    const float* src = g_qkv + (long)b * QKV_BSTRIDE + (long)(512 + c) * NN;
    float acc = 0.f;
    #pragma unroll
    for (int kh = 0; kh < 3; kh++) {
        const int hh = h + kh - 1;
        if (hh < 0 || hh >= 64) continue;
        #pragma unroll
        for (int kw = 0; kw < 3; kw++) {
            const int ww = w + kw - 1;
            if (ww < 0 || ww >= 64) continue;
            acc += src[hh * 64 + ww] * w_pe[c * 9 + kh * 3 + kw];
        }
    }
    g_pe[(long)b * C_BSTRIDE + (long)c * NN + hw] = acc * s[c] + bi[c];
}

// ---- area attention via HMMA (identical to R11 — verified 48us) --------------
#define PITCH 136    // halves per smem row (272B: 16B-divisible, bank-clean)

__global__ __launch_bounds__(256)
void attn_kernel()
{
    __shared__ __align__(16) __half Qs[32][PITCH];
    __shared__ __align__(16) __half Ks[32][PITCH];
    __shared__ __align__(16) __half Vs[32][PITCH];

    const int ba = blockIdx.y >> 3;
    const int h  = blockIdx.y & 7;
    const int q0 = blockIdx.x * 128;
    const int tid  = threadIdx.x;
    const int lane = tid & 31;
    const int wid  = tid >> 5;
    const int wq   = wid * 16;

    const float scale = 0.17677669529663687f * 1.4426950408889634f;

    const long qflat0 = (long)ba * 524288 + (long)(h * HD) * 1024;
    const long kflat0 = qflat0 + 256 * 1024;
    const long vflat0 = (long)ba * 262144 + (long)(h * HD) * 1024;

    const int fd = tid >> 3;
    const int fg = (tid & 7) * 16;

    {
        const long f = qflat0 + (long)fd * 1024 + q0 + fg;
        const float* src = &g_qkv[(f >> 21) * QKV_BSTRIDE + (f & 2097151)];
        __half t[16];
        #pragma unroll
        for (int i = 0; i < 4; i++) {
            const float4 v = *(const float4*)(src + 4 * i);
            t[4*i+0] = __float2half_rn(v.x * scale);
            t[4*i+1] = __float2half_rn(v.y * scale);
            t[4*i+2] = __float2half_rn(v.z * scale);
            t[4*i+3] = __float2half_rn(v.w * scale);
        }
        *(uint4*)&Qs[fd][fg]     = *(uint4*)&t[0];
        *(uint4*)&Qs[fd][fg + 8] = *(uint4*)&t[8];
    }
    __syncthreads();

    unsigned aq[2][4];
    #pragma unroll
    for (int dc = 0; dc < 2; dc++) {
        const int row = dc * 16 + (lane & 7) + ((lane >> 4) & 1) * 8;
        const int col = wq + ((lane >> 3) & 1) * 8;
        ldsm4t(aq[dc], smem_u32(&Qs[row][col]));
    }

    float oacc[4][4] = {};
    float lsum0 = 0.f, lsum1 = 0.f;

    for (int m0 = 0; m0 < NA; m0 += 128) {
        __syncthreads();
        {
            const long fk = kflat0 + (long)fd * 1024 + m0 + fg;
            const float* sk = &g_qkv[(fk >> 21) * QKV_BSTRIDE + (fk & 2097151)];
            __half t[16];
            #pragma unroll
            for (int i = 0; i < 4; i++) {
                const float4 v = *(const float4*)(sk + 4 * i);
                t[4*i+0] = __float2half_rn(v.x);
                t[4*i+1] = __float2half_rn(v.y);
                t[4*i+2] = __float2half_rn(v.z);
                t[4*i+3] = __float2half_rn(v.w);
            }
            *(uint4*)&Ks[fd][fg]     = *(uint4*)&t[0];
            *(uint4*)&Ks[fd][fg + 8] = *(uint4*)&t[8];

            const long fv = vflat0 + (long)fd * 1024 + m0 + fg;
            const float* sv = &g_qkv[(fv >> 20) * QKV_BSTRIDE + 512 * NN + (fv & 1048575)];
            #pragma unroll
            for (int i = 0; i < 4; i++) {
                const float4 v = *(const float4*)(sv + 4 * i);
                t[4*i+0] = __float2half_rn(v.x);
                t[4*i+1] = __float2half_rn(v.y);
                t[4*i+2] = __float2half_rn(v.z);
                t[4*i+3] = __float2half_rn(v.w);
            }
            *(uint4*)&Vs[fd][fg]     = *(uint4*)&t[0];
            *(uint4*)&Vs[fd][fg + 8] = *(uint4*)&t[8];
        }
        __syncthreads();

        float sacc[16][4];
        #pragma unroll
        for (int nt = 0; nt < 16; nt++) {
            sacc[nt][0] = 0.f; sacc[nt][1] = 0.f;
            sacc[nt][2] = 0.f; sacc[nt][3] = 0.f;
        }
        #pragma unroll
        for (int dc = 0; dc < 2; dc++) {
            #pragma unroll
            for (int ntp = 0; ntp < 8; ntp++) {
                unsigned bk[4];
                const int row = dc * 16 + (lane & 7) + ((lane >> 3) & 1) * 8;
                const int col = ntp * 16 + ((lane >> 4) & 1) * 8;
                ldsm4t(bk, smem_u32(&Ks[row][col]));
                mma16816(sacc[2 * ntp],     aq[dc], bk[0], bk[1]);
                mma16816(sacc[2 * ntp + 1], aq[dc], bk[2], bk[3]);
            }
        }
        #pragma unroll
        for (int nt = 0; nt < 16; nt++) {
            sacc[nt][0] = ex2(sacc[nt][0]);
            sacc[nt][1] = ex2(sacc[nt][1]);
            sacc[nt][2] = ex2(sacc[nt][2]);
            sacc[nt][3] = ex2(sacc[nt][3]);
            lsum0 += sacc[nt][0] + sacc[nt][1];
            lsum1 += sacc[nt][2] + sacc[nt][3];
        }
        #pragma unroll
        for (int kt = 0; kt < 8; kt++) {
            unsigned pa[4];
            pa[0] = pkh2(sacc[2 * kt][0],     sacc[2 * kt][1]);
            pa[1] = pkh2(sacc[2 * kt][2],     sacc[2 * kt][3]);
            pa[2] = pkh2(sacc[2 * kt + 1][0], sacc[2 * kt + 1][1]);
            pa[3] = pkh2(sacc[2 * kt + 1][2], sacc[2 * kt + 1][3]);
            #pragma unroll
            for (int dtp = 0; dtp < 2; dtp++) {
                unsigned bv[4];
                const int row = dtp * 16 + (lane & 7) + ((lane >> 4) & 1) * 8;
                const int col = kt * 16 + ((lane >> 3) & 1) * 8;
                ldsm4(bv, smem_u32(&Vs[row][col]));
                mma16816(oacc[2 * dtp],     pa, bv[0], bv[1]);
                mma16816(oacc[2 * dtp + 1], pa, bv[2], bv[3]);
            }
        }
    }

    lsum0 += __shfl_xor_sync(0xffffffff, lsum0, 1);
    lsum0 += __shfl_xor_sync(0xffffffff, lsum0, 2);
    lsum1 += __shfl_xor_sync(0xffffffff, lsum1, 1);
    lsum1 += __shfl_xor_sync(0xffffffff, lsum1, 2);
    const float inv0 = 1.f / lsum0;
    const float inv1 = 1.f / lsum1;

    const int qg = q0 + wq + (lane >> 2);
    #pragma unroll
    for (int dt = 0; dt < 4; dt++) {
        const int d = dt * 8 + (lane & 3) * 2;
        #pragma unroll
        for (int e = 0; e < 2; e++) {
            const long f0 = vflat0 + (long)(d + e) * 1024 + qg;
            g_att[(f0 >> 20) * C_BSTRIDE + (f0 & 1048575)] = oacc[dt][e] * inv0;
            const long f1 = f0 + 8;
            g_att[(f1 >> 20) * C_BSTRIDE + (f1 & 1048575)] = oacc[dt][2 + e] * inv1;
        }
    }
}

// ---------------- launch -------------------------------------------------------
extern "C" void kernel_launch(void* const* d_in, const int* in_sizes, int n_in,
                              void* d_out, int out_size)
{
    const float* x      = (const float*)d_in[0];
    const float* w_qk   = (const float*)d_in[1];
    const float* s_qk   = (const float*)d_in[2];
    const float* b_qk   = (const float*)d_in[3];
    const float* w_v    = (const float*)d_in[4];
    const float* s_v    = (const float*)d_in[5];
    const float* b_v    = (const float*)d_in[6];
    const float* w_pe   = (const float*)d_in[7];
    const float* s_pe   = (const float*)d_in[8];
    const float* b_pe   = (const float*)d_in[9];
    const float* w_proj = (const float*)d_in[10];
    const float* s_proj = (const float*)d_in[11];
    const float* b_proj = (const float*)d_in[12];
    const float* w_m1   = (const float*)d_in[13];
    const float* s_m1   = (const float*)d_in[14];
    const float* b_m1   = (const float*)d_in[15];
    const float* w_m2   = (const float*)d_in[16];
    const float* s_m2   = (const float*)d_in[17];
    const float* b_m2   = (const float*)d_in[18];
    float* out = (float*)d_out;

    float *qkv, *pe, *att, *x1, *mb;
    cudaGetSymbolAddress((void**)&qkv, g_qkv);
    cudaGetSymbolAddress((void**)&pe,  g_pe);
    cudaGetSymbolAddress((void**)&att, g_att);
    cudaGetSymbolAddress((void**)&x1,  g_x1);
    cudaGetSymbolAddress((void**)&mb,  g_m);

    // qk -> g_qkv channels [0,512)   (M=512 -> 4 m-blocks of 128)
    gemm_kernel<<<dim3(32, 4, BSZ), 256>>>(w_qk, x, nullptr, s_qk, b_qk, nullptr,
        qkv, 512, 256, (long)C_BSTRIDE, (long)QKV_BSTRIDE, 0, 0);
    // v -> g_qkv channels [512,768)  (M=256 -> 2)
    gemm_kernel<<<dim3(32, 2, BSZ), 256>>>(w_v, x, nullptr, s_v, b_v, nullptr,
        qkv + 512 * NN, 256, 256, (long)C_BSTRIDE, (long)QKV_BSTRIDE, 0, 0);
    // pe = dwconv3x3(v)
    dwconv_kernel<<<dim3(16, BSZ * CC), 256>>>(w_pe, s_pe, b_pe);
    // area attention -> g_att
    attn_kernel<<<dim3(NA / 128, BA * HEADS), 256>>>();
    // x1 = x + conv1x1(att + pe, w_proj)
    gemm_kernel<<<dim3(32, 2, BSZ), 256>>>(w_proj, att, pe, s_proj, b_proj, x,
        x1, 256, 256, (long)C_BSTRIDE, (long)C_BSTRIDE, (long)C_BSTRIDE, 0);
    // m = silu(conv1x1(x1, w_m1))    (M=307 -> 3)
    gemm_kernel<<<dim3(32, 3, BSZ), 256>>>(w_m1, x1, nullptr, s_m1, b_m1, nullptr,
        mb, MLPD, 256, (long)C_BSTRIDE, (long)MLPD * NN, 0, 1);
    // out = x1 + conv1x1(m, w_m2)    (K=307 -> scalar A loads)
    gemm_kernel<<<dim3(32, 2, BSZ), 256>>>(w_m2, mb, nullptr, s_m2, b_m2, x1,
        out, 256, MLPD, (long)MLPD * NN, (long)C_BSTRIDE, (long)C_BSTRIDE, 0);
}